// round 12
// baseline (speedup 1.0000x reference)
#include <cuda_runtime.h>
#include <cuda_fp16.h>
#include <cstdint>

// ---------------------------------------------------------------------------
// Problem constants
// ---------------------------------------------------------------------------
#define NBATCH 8192
#define SEQ    6
#define TOK    49152        // NBATCH * SEQ
#define DM     2048
#define NH     16
#define DH     128
#define LN_EPS 1e-5f

// ---------------------------------------------------------------------------
// GEMM tiling: CTA 128x128, BK=64 halves, 3 stages, 256 threads (8 warps 32x64)
// Swizzled smem (no padding): row = 64 halves = 8 x 16B chunks, chunk ^= row&7
// ---------------------------------------------------------------------------
#define TBM 128
#define TBN 128
#define TBK 64
#define STAGES 3
#define KITERS (DM / TBK)                      // 32 (power of 2)
#define A_HALVES (TBM * TBK)                   // 8192
#define STAGE_HALVES ((TBM + TBN) * TBK)       // 16384 halves = 32 KB
#define DYN_SMEM_BYTES (STAGES * STAGE_HALVES * 2)   // 98304 B
#define EPI_LD  132                            // fp32 epilogue stride (floats)
#define EPI_LDH 136                            // fp16 epilogue stride (halves)

// ---------------------------------------------------------------------------
// Device-global scratch
// ---------------------------------------------------------------------------
__device__ __align__(256) __half g_Xh[(size_t)TOK * DM];   // LN out / attn out
__device__ __align__(256) __half g_Q[(size_t)TOK * DM];
__device__ __align__(256) __half g_K[(size_t)TOK * DM];
__device__ __align__(256) __half g_V[(size_t)TOK * DM];
__device__ __align__(256) __half g_Wh[4][(size_t)DM * DM]; // fp16 weights (q,k,v,o)
__device__ __align__(16)  float  g_mask[SEQ * SEQ];        // sigmoid(routing)/sqrt(DH)

// ---------------------------------------------------------------------------
// helpers
// ---------------------------------------------------------------------------
__device__ __forceinline__ void cp_async16(void* smem_dst, const void* gmem_src) {
    unsigned s = (unsigned)__cvta_generic_to_shared(smem_dst);
    asm volatile("cp.async.cg.shared.global [%0], [%1], 16;\n" :: "r"(s), "l"(gmem_src));
}
__device__ __forceinline__ void cp_commit() {
    asm volatile("cp.async.commit_group;\n" ::: "memory");
}
template <int N>
__device__ __forceinline__ void cp_wait() {
    asm volatile("cp.async.wait_group %0;\n" :: "n"(N) : "memory");
}
__device__ __forceinline__ void ldsm_x4(uint32_t& d0, uint32_t& d1, uint32_t& d2,
                                        uint32_t& d3, const __half* p) {
    uint32_t a = (uint32_t)__cvta_generic_to_shared(p);
    asm volatile("ldmatrix.sync.aligned.m8n8.x4.shared.b16 {%0,%1,%2,%3}, [%4];"
                 : "=r"(d0), "=r"(d1), "=r"(d2), "=r"(d3) : "r"(a));
}
__device__ __forceinline__ void mma16816(float* c,
                                         uint32_t a0, uint32_t a1, uint32_t a2, uint32_t a3,
                                         uint32_t b0, uint32_t b1) {
    asm volatile("mma.sync.aligned.m16n8k16.row.col.f32.f16.f16.f32 "
                 "{%0,%1,%2,%3}, {%4,%5,%6,%7}, {%8,%9}, {%0,%1,%2,%3};"
                 : "+f"(c[0]), "+f"(c[1]), "+f"(c[2]), "+f"(c[3])
                 : "r"(a0), "r"(a1), "r"(a2), "r"(a3), "r"(b0), "r"(b1));
}

// ---------------------------------------------------------------------------
// Weight convert (all 4 weights, one launch): fp32 -> fp16
// ---------------------------------------------------------------------------
__global__ void __launch_bounds__(256) w2h_all_kernel(
    const float* __restrict__ w0, const float* __restrict__ w1,
    const float* __restrict__ w2, const float* __restrict__ w3,
    __half* __restrict__ out)
{
    const float* src_f = (blockIdx.y == 0) ? w0 : (blockIdx.y == 1) ? w1
                       : (blockIdx.y == 2) ? w2 : w3;
    __half* dst_h = out + (size_t)blockIdx.y * DM * DM;
    const int n4 = DM * DM / 4;
    int i = blockIdx.x * 256 + threadIdx.x;
    int stride = gridDim.x * 256;
    const float4* src = (const float4*)src_f;
    __half2* dst = (__half2*)dst_h;
    for (; i < n4; i += stride) {
        float4 v = src[i];
        dst[i * 2 + 0] = __floats2half2_rn(v.x, v.y);
        dst[i * 2 + 1] = __floats2half2_rn(v.z, v.w);
    }
}

// ---------------------------------------------------------------------------
// LayerNorm: one block (256 threads) per token, D = 2048. fp16 output.
// Single __syncthreads; block 0 also precomputes the routing mask.
// ---------------------------------------------------------------------------
__global__ void __launch_bounds__(256) ln_kernel(
    const float* __restrict__ x, const float* __restrict__ gamma,
    const float* __restrict__ beta, const float* __restrict__ routing,
    float* __restrict__ maskOut, __half* __restrict__ out)
{
    int t   = blockIdx.x;
    int tid = threadIdx.x;

    if (t == 0 && tid < SEQ * SEQ) {
        float r = routing[tid];
        maskOut[tid] = 0.08838834764831845f / (1.f + __expf(-r));
    }

    const float4* xr = (const float4*)(x + (size_t)t * DM);

    float4 a = xr[tid];
    float4 b = xr[tid + 256];
    float s  = a.x + a.y + a.z + a.w + b.x + b.y + b.z + b.w;
    float ss = a.x*a.x + a.y*a.y + a.z*a.z + a.w*a.w
             + b.x*b.x + b.y*b.y + b.z*b.z + b.w*b.w;

    __shared__ float red[2][8];
    #pragma unroll
    for (int o = 16; o; o >>= 1) {
        s  += __shfl_xor_sync(0xffffffffu, s,  o);
        ss += __shfl_xor_sync(0xffffffffu, ss, o);
    }
    int wid = tid >> 5, lane = tid & 31;
    if (lane == 0) { red[0][wid] = s; red[1][wid] = ss; }
    __syncthreads();

    float st = 0.f, sst = 0.f;
    #pragma unroll
    for (int i = 0; i < 8; i++) { st += red[0][i]; sst += red[1][i]; }

    float mu  = st * (1.f / DM);
    float var = sst * (1.f / DM) - mu * mu;
    float inv = rsqrtf(var + LN_EPS);

    const float4* g4 = (const float4*)gamma;
    const float4* b4 = (const float4*)beta;
    __half2* o2 = (__half2*)(out + (size_t)t * DM);

    float4 ga = g4[tid],       ba = b4[tid];
    float4 gb = g4[tid + 256], bb = b4[tid + 256];
    o2[tid * 2 + 0] = __floats2half2_rn((a.x - mu) * inv * ga.x + ba.x,
                                        (a.y - mu) * inv * ga.y + ba.y);
    o2[tid * 2 + 1] = __floats2half2_rn((a.z - mu) * inv * ga.z + ba.z,
                                        (a.w - mu) * inv * ga.w + ba.w);
    o2[(tid + 256) * 2 + 0] = __floats2half2_rn((b.x - mu) * inv * gb.x + bb.x,
                                                (b.y - mu) * inv * gb.y + bb.y);
    o2[(tid + 256) * 2 + 1] = __floats2half2_rn((b.z - mu) * inv * gb.z + bb.z,
                                                (b.w - mu) * inv * gb.w + bb.w);
}

// ---------------------------------------------------------------------------
// Core fp16 mma GEMM body: one 128x128 tile of A @ Wrow^T.
// 8 warps: wm = wid&3 (32 rows), wn = wid>>2 (64 cols). 3-stage cp.async,
// one __syncthreads per k-iter, B-fragment ping-pong prefetch.
// `phase` rotates the K-iteration start (desyncs co-resident CTAs).
// ---------------------------------------------------------------------------
template <typename OutT>
__device__ __forceinline__ void gemm_tile(
    const __half* __restrict__ Ab,   // A + m0*DM
    const __half* __restrict__ Wb,   // W row block
    const float* __restrict__ bias,  // bias + n0 (block of 128)
    const float* __restrict__ resid, // resid + m0*DM + n0, or null
    OutT* __restrict__ Cb,           // C + m0*ldc + n0
    int ldc, char* smem_raw, int tid, int phase)
{
    __half* smem = (__half*)smem_raw;
    const int wid  = tid >> 5;
    const int lane = tid & 31;
    const int wm   = wid & 3;
    const int wn   = wid >> 2;

    float acc[2][8][4];
    #pragma unroll
    for (int i = 0; i < 2; i++)
        #pragma unroll
        for (int j = 0; j < 8; j++)
            #pragma unroll
            for (int e = 0; e < 4; e++)
                acc[i][j][e] = 0.f;

    const int a_row_l = lane & 15;
    const int a_ksel  = lane >> 4;
    const int b_row_l = ((lane >> 4) << 3) | (lane & 7);
    const int b_ksel  = (lane >> 3) & 1;

    auto load_stage = [&](int buf, int st) {
        __half* sa = smem + (size_t)buf * STAGE_HALVES;
        __half* sb = sa + A_HALVES;
        int k0 = ((st + phase) & (KITERS - 1)) * TBK;
        #pragma unroll
        for (int u = 0; u < 4; u++) {
            int idx = tid + u * 256;
            int row = idx >> 3, c = idx & 7;
            int pc  = c ^ (row & 7);
            cp_async16(sa + row * TBK + pc * 8, Ab + (size_t)row * DM + k0 + c * 8);
        }
        #pragma unroll
        for (int u = 0; u < 4; u++) {
            int idx = tid + u * 256;
            int row = idx >> 3, c = idx & 7;
            int pc  = c ^ (row & 7);
            cp_async16(sb + row * TBK + pc * 8, Wb + (size_t)row * DM + k0 + c * 8);
        }
    };

    load_stage(0, 0); cp_commit();
    load_stage(1, 1); cp_commit();

    for (int k = 0; k < KITERS; k++) {
        int buf = k % STAGES;
        cp_wait<STAGES - 2>();
        __syncthreads();

        if (k + 2 < KITERS) load_stage((k + 2) % STAGES, k + 2);
        cp_commit();

        const __half* sa = smem + (size_t)buf * STAGE_HALVES;
        const __half* sb = sa + A_HALVES;

        // B ping-pong prefetch across 4 k16 steps
        uint32_t b[2][4][4];
        #pragma unroll
        for (int nj = 0; nj < 4; nj++) {
            int row = wn * 64 + nj * 16 + b_row_l;
            int ch  = (0 + b_ksel) ^ (row & 7);
            ldsm_x4(b[0][nj][0], b[0][nj][1], b[0][nj][2], b[0][nj][3],
                    sb + row * TBK + ch * 8);
        }

        #pragma unroll
        for (int kk4 = 0; kk4 < 4; kk4++) {
            const int kbase = kk4 * 2;
            const int cur = kk4 & 1, nxt = cur ^ 1;

            if (kk4 < 3) {
                #pragma unroll
                for (int nj = 0; nj < 4; nj++) {
                    int row = wn * 64 + nj * 16 + b_row_l;
                    int ch  = (kbase + 2 + b_ksel) ^ (row & 7);
                    ldsm_x4(b[nxt][nj][0], b[nxt][nj][1], b[nxt][nj][2], b[nxt][nj][3],
                            sb + row * TBK + ch * 8);
                }
            }

            uint32_t a[2][4];
            #pragma unroll
            for (int mi = 0; mi < 2; mi++) {
                int row = wm * 32 + mi * 16 + a_row_l;
                int ch  = (kbase + a_ksel) ^ (row & 7);
                ldsm_x4(a[mi][0], a[mi][1], a[mi][2], a[mi][3],
                        sa + row * TBK + ch * 8);
            }
            #pragma unroll
            for (int mi = 0; mi < 2; mi++)
                #pragma unroll
                for (int nj = 0; nj < 4; nj++) {
                    mma16816(acc[mi][nj * 2 + 0],
                             a[mi][0], a[mi][1], a[mi][2], a[mi][3],
                             b[cur][nj][0], b[cur][nj][1]);
                    mma16816(acc[mi][nj * 2 + 1],
                             a[mi][0], a[mi][1], a[mi][2], a[mi][3],
                             b[cur][nj][2], b[cur][nj][3]);
                }
        }
    }

    __syncthreads();

    if constexpr (sizeof(OutT) == 2) {
        // fp16 epilogue: add bias in regs, stage half2, copy out 16B chunks
        __half* epsH = (__half*)smem_raw;
        {
            int r = lane >> 2;
            int cc = (lane & 3) * 2;
            #pragma unroll
            for (int mi = 0; mi < 2; mi++) {
                int row0 = wm * 32 + mi * 16;
                #pragma unroll
                for (int nj = 0; nj < 8; nj++) {
                    int col0 = wn * 64 + nj * 8 + cc;
                    float2 bv = *(const float2*)(bias + col0);
                    __half2 h0 = __floats2half2_rn(acc[mi][nj][0] + bv.x,
                                                   acc[mi][nj][1] + bv.y);
                    __half2 h1 = __floats2half2_rn(acc[mi][nj][2] + bv.x,
                                                   acc[mi][nj][3] + bv.y);
                    *(__half2*)(epsH + (size_t)(row0 + r) * EPI_LDH + col0) = h0;
                    *(__half2*)(epsH + (size_t)(row0 + r + 8) * EPI_LDH + col0) = h1;
                }
            }
        }
        __syncthreads();
        #pragma unroll
        for (int u = 0; u < 8; u++) {
            int idx = tid + u * 256;          // 0..2047
            int row = idx >> 4;               // 0..127
            int c8  = (idx & 15) * 8;         // 0..120
            *(uint4*)((__half*)Cb + (size_t)row * ldc + c8) =
                *(const uint4*)(epsH + (size_t)row * EPI_LDH + c8);
        }
    } else {
        // fp32 epilogue with residual
        float* eps = (float*)smem_raw;
        {
            int r = lane >> 2;
            int cc = (lane & 3) * 2;
            #pragma unroll
            for (int mi = 0; mi < 2; mi++) {
                int row0 = wm * 32 + mi * 16;
                #pragma unroll
                for (int nj = 0; nj < 8; nj++) {
                    int col0 = wn * 64 + nj * 8 + cc;
                    float* e0 = eps + (size_t)(row0 + r) * EPI_LD + col0;
                    float* e1 = eps + (size_t)(row0 + r + 8) * EPI_LD + col0;
                    e0[0] = acc[mi][nj][0];
                    e0[1] = acc[mi][nj][1];
                    e1[0] = acc[mi][nj][2];
                    e1[1] = acc[mi][nj][3];
                }
            }
        }
        __syncthreads();
        #pragma unroll
        for (int u = 0; u < 16; u++) {
            int idx = tid + u * 256;
            int row = idx >> 5;
            int c4  = (idx & 31) * 4;
            const float* ep = eps + (size_t)row * EPI_LD + c4;
            float4 bv = *(const float4*)(bias + c4);
            float4 o;
            o.x = ep[0] + bv.x;
            o.y = ep[1] + bv.y;
            o.z = ep[2] + bv.z;
            o.w = ep[3] + bv.w;
            float4 rv = *(const float4*)(resid + (size_t)row * DM + c4);
            o.x += rv.x; o.y += rv.y; o.z += rv.z; o.w += rv.w;
            *(float4*)((float*)Cb + (size_t)row * ldc + c4) = o;
        }
    }
}

// ---------------------------------------------------------------------------
// Fused QKV GEMM: grid (48, 384). blockIdx.x selects matrix (Q/K/V) + column.
// ---------------------------------------------------------------------------
__global__ void __launch_bounds__(256, 2) gemm_qkv_kernel(
    const __half* __restrict__ A, const __half* __restrict__ Wcat,
    const float* __restrict__ bq, const float* __restrict__ bk,
    const float* __restrict__ bv,
    __half* __restrict__ Q, __half* __restrict__ K, __half* __restrict__ V)
{
    extern __shared__ __align__(16) char smem_raw[];
    const int which = blockIdx.x >> 4;              // 0=Q, 1=K, 2=V
    const int ncol  = (blockIdx.x & 15) * TBN;
    const int m0    = blockIdx.y * TBM;
    const int phase = ((blockIdx.x + blockIdx.y) & 1) * (KITERS / 2);

    const __half* Ab = A + (size_t)m0 * DM;
    const __half* Wb = Wcat + ((size_t)which * DM + ncol) * DM;
    const float*  bs = (which == 0) ? bq : (which == 1) ? bk : bv;
    __half* Cb = ((which == 0) ? Q : (which == 1) ? K : V)
               + (size_t)m0 * DM + ncol;

    gemm_tile<__half>(Ab, Wb, bs + ncol, nullptr, Cb, DM, smem_raw,
                      threadIdx.x, phase);
}

// ---------------------------------------------------------------------------
// Output projection GEMM (+bias +residual), fp32 out: grid (16, 384)
// ---------------------------------------------------------------------------
__global__ void __launch_bounds__(256, 2) gemm_o_kernel(
    const __half* __restrict__ A, const __half* __restrict__ W,
    const float* __restrict__ bias, const float* __restrict__ resid,
    float* __restrict__ C)
{
    extern __shared__ __align__(16) char smem_raw[];
    const int ncol = blockIdx.x * TBN;
    const int m0   = blockIdx.y * TBM;
    const int phase = ((blockIdx.x + blockIdx.y) & 1) * (KITERS / 2);

    gemm_tile<float>(A + (size_t)m0 * DM,
                     W + (size_t)ncol * DM,
                     bias + ncol,
                     resid + (size_t)m0 * DM + ncol,
                     C + (size_t)m0 * DM + ncol,
                     DM, smem_raw, threadIdx.x, phase);
}

// ---------------------------------------------------------------------------
// Attention: one warp per (batch, head). S=6, DH=128; lane owns 4 head dims.
// Precomputed mask = sigmoid(routing)/sqrt(DH); __expf softmax; V-load overlap.
// ---------------------------------------------------------------------------
__global__ void __launch_bounds__(128) attn_kernel(
    const __half* __restrict__ Q, const __half* __restrict__ K,
    const __half* __restrict__ V, const float* __restrict__ mask,
    __half* __restrict__ O)
{
    int wg   = blockIdx.x * 4 + (threadIdx.x >> 5);
    int lane = threadIdx.x & 31;
    int b = wg >> 4, h = wg & 15;
    size_t base = (size_t)b * SEQ * DM + (size_t)h * DH + lane * 4;

    float4 q[SEQ], k[SEQ];
    #pragma unroll
    for (int s = 0; s < SEQ; s++) {
        const __half2* qp = (const __half2*)(Q + base + (size_t)s * DM);
        const __half2* kp = (const __half2*)(K + base + (size_t)s * DM);
        float2 q0 = __half22float2(qp[0]), q1 = __half22float2(qp[1]);
        float2 k0 = __half22float2(kp[0]), k1 = __half22float2(kp[1]);
        q[s] = make_float4(q0.x, q0.y, q1.x, q1.y);
        k[s] = make_float4(k0.x, k0.y, k1.x, k1.y);
    }

    float sc[SEQ * SEQ];
    #pragma unroll
    for (int i = 0; i < SEQ; i++)
        #pragma unroll
        for (int j = 0; j < SEQ; j++)
            sc[i * SEQ + j] = q[i].x * k[j].x + q[i].y * k[j].y
                            + q[i].z * k[j].z + q[i].w * k[j].w;

    // kick off V loads; latency hidden under the shuffle chain
    uint2 vraw[SEQ];
    #pragma unroll
    for (int s = 0; s < SEQ; s++)
        vraw[s] = *(const uint2*)(V + base + (size_t)s * DM);

    #pragma unroll
    for (int t = 0; t < SEQ * SEQ; t++)
        #pragma unroll
        for (int o = 16; o; o >>= 1)
            sc[t] += __shfl_xor_sync(0xffffffffu, sc[t], o);

    #pragma unroll
    for (int i = 0; i < SEQ; i++)
        #pragma unroll
        for (int j = 0; j < SEQ; j++)
            sc[i * SEQ + j] *= __ldg(mask + i * SEQ + j);

    #pragma unroll
    for (int i = 0; i < SEQ; i++) {
        float mx = sc[i * SEQ];
        #pragma unroll
        for (int j = 1; j < SEQ; j++) mx = fmaxf(mx, sc[i * SEQ + j]);
        float sum = 0.f;
        #pragma unroll
        for (int j = 0; j < SEQ; j++) {
            sc[i * SEQ + j] = __expf(sc[i * SEQ + j] - mx);
            sum += sc[i * SEQ + j];
        }
        float rs = 1.f / sum;
        #pragma unroll
        for (int j = 0; j < SEQ; j++) sc[i * SEQ + j] *= rs;
    }

    float4 v[SEQ];
    #pragma unroll
    for (int s = 0; s < SEQ; s++) {
        __half2 h0 = *(__half2*)&vraw[s].x;
        __half2 h1 = *(__half2*)&vraw[s].y;
        float2 v0 = __half22float2(h0), v1 = __half22float2(h1);
        v[s] = make_float4(v0.x, v0.y, v1.x, v1.y);
    }

    #pragma unroll
    for (int i = 0; i < SEQ; i++) {
        float4 o = make_float4(0.f, 0.f, 0.f, 0.f);
        #pragma unroll
        for (int j = 0; j < SEQ; j++) {
            float p = sc[i * SEQ + j];
            o.x += p * v[j].x; o.y += p * v[j].y;
            o.z += p * v[j].z; o.w += p * v[j].w;
        }
        __half2* dst = (__half2*)(O + base + (size_t)i * DM);
        dst[0] = __floats2half2_rn(o.x, o.y);
        dst[1] = __floats2half2_rn(o.z, o.w);
    }
}

// ---------------------------------------------------------------------------
// kernel_launch
// inputs: 0 stream_embeddings, 1 Wq, 2 bq, 3 Wk, 4 bk, 5 Wv, 6 bv,
//         7 Wo, 8 bo, 9 routing_logits, 10 gamma, 11 beta
// ---------------------------------------------------------------------------
extern "C" void kernel_launch(void* const* d_in, const int* in_sizes, int n_in,
                              void* d_out, int out_size)
{
    (void)in_sizes; (void)n_in; (void)out_size;
    const float* x       = (const float*)d_in[0];
    const float* Wq      = (const float*)d_in[1];
    const float* bq      = (const float*)d_in[2];
    const float* Wk      = (const float*)d_in[3];
    const float* bk      = (const float*)d_in[4];
    const float* Wv      = (const float*)d_in[5];
    const float* bv      = (const float*)d_in[6];
    const float* Wo      = (const float*)d_in[7];
    const float* bo      = (const float*)d_in[8];
    const float* routing = (const float*)d_in[9];
    const float* gamma   = (const float*)d_in[10];
    const float* beta    = (const float*)d_in[11];
    float* out = (float*)d_out;

    __half *Xh, *Qb, *Kb, *Vb, *Wh;
    float* maskp;
    cudaGetSymbolAddress((void**)&Xh, g_Xh);
    cudaGetSymbolAddress((void**)&Qb, g_Q);
    cudaGetSymbolAddress((void**)&Kb, g_K);
    cudaGetSymbolAddress((void**)&Vb, g_V);
    cudaGetSymbolAddress((void**)&Wh, g_Wh);
    cudaGetSymbolAddress((void**)&maskp, g_mask);
    __half* Woh = Wh + 3 * (size_t)DM * DM;

    cudaFuncSetAttribute(gemm_qkv_kernel,
                         cudaFuncAttributeMaxDynamicSharedMemorySize, DYN_SMEM_BYTES);
    cudaFuncSetAttribute(gemm_qkv_kernel,
                         cudaFuncAttributePreferredSharedMemoryCarveout, 100);
    cudaFuncSetAttribute(gemm_o_kernel,
                         cudaFuncAttributeMaxDynamicSharedMemorySize, DYN_SMEM_BYTES);
    cudaFuncSetAttribute(gemm_o_kernel,
                         cudaFuncAttributePreferredSharedMemoryCarveout, 100);

    w2h_all_kernel<<<dim3(512, 4), 256>>>(Wq, Wk, Wv, Wo, Wh);

    ln_kernel<<<TOK, 256>>>(x, gamma, beta, routing, maskp, Xh);

    gemm_qkv_kernel<<<dim3(48, TOK / TBM), 256, DYN_SMEM_BYTES>>>(
        Xh, Wh, bq, bk, bv, Qb, Kb, Vb);

    attn_kernel<<<(NBATCH * NH) / 4, 128>>>(Qb, Kb, Vb, maskp, Xh);

    gemm_o_kernel<<<dim3(16, TOK / TBM), 256, DYN_SMEM_BYTES>>>(
        Xh, Woh, bo, x /*residual*/, out);
}

// round 13
// speedup vs baseline: 1.0291x; 1.0291x over previous
#include <cuda_runtime.h>
#include <cuda_fp16.h>
#include <cstdint>

// ---------------------------------------------------------------------------
// Problem constants
// ---------------------------------------------------------------------------
#define NBATCH 8192
#define SEQ    6
#define TOK    49152        // NBATCH * SEQ
#define DM     2048
#define NH     16
#define DH     128
#define LN_EPS 1e-5f

// ---------------------------------------------------------------------------
// GEMM tiling: CTA 128x128, BK=64 halves, 3 stages, 256 threads (8 warps 32x64)
// Swizzled smem (no padding): row = 64 halves = 8 x 16B chunks, chunk ^= row&7
// ---------------------------------------------------------------------------
#define TBM 128
#define TBN 128
#define TBK 64
#define STAGES 3
#define KITERS (DM / TBK)                      // 32
#define A_HALVES (TBM * TBK)                   // 8192
#define STAGE_HALVES ((TBM + TBN) * TBK)       // 16384 halves = 32 KB
#define DYN_SMEM_BYTES (STAGES * STAGE_HALVES * 2)   // 98304 B
#define EPI_LD  132                            // fp32 epilogue stride (floats)
#define EPI_LDH 136                            // fp16 epilogue stride (halves)

// ---------------------------------------------------------------------------
// Device-global scratch
// ---------------------------------------------------------------------------
__device__ __align__(256) __half g_Xh[(size_t)TOK * DM];   // LN out / attn out
__device__ __align__(256) __half g_Q[(size_t)TOK * DM];
__device__ __align__(256) __half g_K[(size_t)TOK * DM];
__device__ __align__(256) __half g_V[(size_t)TOK * DM];
__device__ __align__(256) __half g_Wh[4][(size_t)DM * DM]; // fp16 weights (q,k,v,o)
__device__ __align__(16)  float  g_mask[SEQ * SEQ];        // sigmoid(routing)/sqrt(DH)

// ---------------------------------------------------------------------------
// helpers
// ---------------------------------------------------------------------------
__device__ __forceinline__ void cp_async16(void* smem_dst, const void* gmem_src) {
    unsigned s = (unsigned)__cvta_generic_to_shared(smem_dst);
    asm volatile("cp.async.cg.shared.global [%0], [%1], 16;\n" :: "r"(s), "l"(gmem_src));
}
__device__ __forceinline__ void cp_commit() {
    asm volatile("cp.async.commit_group;\n" ::: "memory");
}
template <int N>
__device__ __forceinline__ void cp_wait() {
    asm volatile("cp.async.wait_group %0;\n" :: "n"(N) : "memory");
}
__device__ __forceinline__ void ldsm_x4(uint32_t& d0, uint32_t& d1, uint32_t& d2,
                                        uint32_t& d3, const __half* p) {
    uint32_t a = (uint32_t)__cvta_generic_to_shared(p);
    asm volatile("ldmatrix.sync.aligned.m8n8.x4.shared.b16 {%0,%1,%2,%3}, [%4];"
                 : "=r"(d0), "=r"(d1), "=r"(d2), "=r"(d3) : "r"(a));
}
__device__ __forceinline__ void mma16816(float* c,
                                         uint32_t a0, uint32_t a1, uint32_t a2, uint32_t a3,
                                         uint32_t b0, uint32_t b1) {
    asm volatile("mma.sync.aligned.m16n8k16.row.col.f32.f16.f16.f32 "
                 "{%0,%1,%2,%3}, {%4,%5,%6,%7}, {%8,%9}, {%0,%1,%2,%3};"
                 : "+f"(c[0]), "+f"(c[1]), "+f"(c[2]), "+f"(c[3])
                 : "r"(a0), "r"(a1), "r"(a2), "r"(a3), "r"(b0), "r"(b1));
}

// ---------------------------------------------------------------------------
// Weight convert (all 4 weights, one launch): fp32 -> fp16
// ---------------------------------------------------------------------------
__global__ void __launch_bounds__(256) w2h_all_kernel(
    const float* __restrict__ w0, const float* __restrict__ w1,
    const float* __restrict__ w2, const float* __restrict__ w3,
    __half* __restrict__ out)
{
    const float* src_f = (blockIdx.y == 0) ? w0 : (blockIdx.y == 1) ? w1
                       : (blockIdx.y == 2) ? w2 : w3;
    __half* dst_h = out + (size_t)blockIdx.y * DM * DM;
    const int n4 = DM * DM / 4;
    int i = blockIdx.x * 256 + threadIdx.x;
    int stride = gridDim.x * 256;
    const float4* src = (const float4*)src_f;
    __half2* dst = (__half2*)dst_h;
    for (; i < n4; i += stride) {
        float4 v = src[i];
        dst[i * 2 + 0] = __floats2half2_rn(v.x, v.y);
        dst[i * 2 + 1] = __floats2half2_rn(v.z, v.w);
    }
}

// ---------------------------------------------------------------------------
// LayerNorm: one block (256 threads) per token, D = 2048. fp16 output.
// Single __syncthreads; block 0 also precomputes the routing mask.
// ---------------------------------------------------------------------------
__global__ void __launch_bounds__(256) ln_kernel(
    const float* __restrict__ x, const float* __restrict__ gamma,
    const float* __restrict__ beta, const float* __restrict__ routing,
    float* __restrict__ maskOut, __half* __restrict__ out)
{
    int t   = blockIdx.x;
    int tid = threadIdx.x;

    if (t == 0 && tid < SEQ * SEQ) {
        float r = routing[tid];
        maskOut[tid] = 0.08838834764831845f / (1.f + __expf(-r));
    }

    const float4* xr = (const float4*)(x + (size_t)t * DM);

    float4 a = xr[tid];
    float4 b = xr[tid + 256];
    float s  = a.x + a.y + a.z + a.w + b.x + b.y + b.z + b.w;
    float ss = a.x*a.x + a.y*a.y + a.z*a.z + a.w*a.w
             + b.x*b.x + b.y*b.y + b.z*b.z + b.w*b.w;

    __shared__ float red[2][8];
    #pragma unroll
    for (int o = 16; o; o >>= 1) {
        s  += __shfl_xor_sync(0xffffffffu, s,  o);
        ss += __shfl_xor_sync(0xffffffffu, ss, o);
    }
    int wid = tid >> 5, lane = tid & 31;
    if (lane == 0) { red[0][wid] = s; red[1][wid] = ss; }
    __syncthreads();

    float st = 0.f, sst = 0.f;
    #pragma unroll
    for (int i = 0; i < 8; i++) { st += red[0][i]; sst += red[1][i]; }

    float mu  = st * (1.f / DM);
    float var = sst * (1.f / DM) - mu * mu;
    float inv = rsqrtf(var + LN_EPS);

    const float4* g4 = (const float4*)gamma;
    const float4* b4 = (const float4*)beta;
    __half2* o2 = (__half2*)(out + (size_t)t * DM);

    float4 ga = g4[tid],       ba = b4[tid];
    float4 gb = g4[tid + 256], bb = b4[tid + 256];
    o2[tid * 2 + 0] = __floats2half2_rn((a.x - mu) * inv * ga.x + ba.x,
                                        (a.y - mu) * inv * ga.y + ba.y);
    o2[tid * 2 + 1] = __floats2half2_rn((a.z - mu) * inv * ga.z + ba.z,
                                        (a.w - mu) * inv * ga.w + ba.w);
    o2[(tid + 256) * 2 + 0] = __floats2half2_rn((b.x - mu) * inv * gb.x + bb.x,
                                                (b.y - mu) * inv * gb.y + bb.y);
    o2[(tid + 256) * 2 + 1] = __floats2half2_rn((b.z - mu) * inv * gb.z + bb.z,
                                                (b.w - mu) * inv * gb.w + bb.w);
}

// ---------------------------------------------------------------------------
// Core fp16 mma GEMM body (R8/R10-proven schedule): one 128x128 tile.
// 8 warps: wm = wid&3 (32 rows), wn = wid>>2 (64 cols). 3-stage cp.async,
// one __syncthreads per k-iter, B-fragment ping-pong prefetch. No K-phase
// rotation: co-resident CTAs sweeping the same K-slice is what gives the
// fused-QKV launch its L2 temporal locality (R11 post-mortem).
// ---------------------------------------------------------------------------
template <typename OutT>
__device__ __forceinline__ void gemm_tile(
    const __half* __restrict__ Ab,   // A + m0*DM
    const __half* __restrict__ Wb,   // W row block
    const float* __restrict__ bias,  // bias + n0 (block of 128)
    const float* __restrict__ resid, // resid + m0*DM + n0, or null
    OutT* __restrict__ Cb,           // C + m0*ldc + n0
    int ldc, char* smem_raw, int tid)
{
    __half* smem = (__half*)smem_raw;
    const int wid  = tid >> 5;
    const int lane = tid & 31;
    const int wm   = wid & 3;
    const int wn   = wid >> 2;

    float acc[2][8][4];
    #pragma unroll
    for (int i = 0; i < 2; i++)
        #pragma unroll
        for (int j = 0; j < 8; j++)
            #pragma unroll
            for (int e = 0; e < 4; e++)
                acc[i][j][e] = 0.f;

    const int a_row_l = lane & 15;
    const int a_ksel  = lane >> 4;
    const int b_row_l = ((lane >> 4) << 3) | (lane & 7);
    const int b_ksel  = (lane >> 3) & 1;

    auto load_stage = [&](int buf, int st) {
        __half* sa = smem + (size_t)buf * STAGE_HALVES;
        __half* sb = sa + A_HALVES;
        int k0 = st * TBK;
        #pragma unroll
        for (int u = 0; u < 4; u++) {
            int idx = tid + u * 256;
            int row = idx >> 3, c = idx & 7;
            int pc  = c ^ (row & 7);
            cp_async16(sa + row * TBK + pc * 8, Ab + (size_t)row * DM + k0 + c * 8);
        }
        #pragma unroll
        for (int u = 0; u < 4; u++) {
            int idx = tid + u * 256;
            int row = idx >> 3, c = idx & 7;
            int pc  = c ^ (row & 7);
            cp_async16(sb + row * TBK + pc * 8, Wb + (size_t)row * DM + k0 + c * 8);
        }
    };

    load_stage(0, 0); cp_commit();
    load_stage(1, 1); cp_commit();

    for (int k = 0; k < KITERS; k++) {
        int buf = k % STAGES;
        cp_wait<STAGES - 2>();
        __syncthreads();

        if (k + 2 < KITERS) load_stage((k + 2) % STAGES, k + 2);
        cp_commit();

        const __half* sa = smem + (size_t)buf * STAGE_HALVES;
        const __half* sb = sa + A_HALVES;

        // B ping-pong prefetch across 4 k16 steps
        uint32_t b[2][4][4];
        #pragma unroll
        for (int nj = 0; nj < 4; nj++) {
            int row = wn * 64 + nj * 16 + b_row_l;
            int ch  = (0 + b_ksel) ^ (row & 7);
            ldsm_x4(b[0][nj][0], b[0][nj][1], b[0][nj][2], b[0][nj][3],
                    sb + row * TBK + ch * 8);
        }

        #pragma unroll
        for (int kk4 = 0; kk4 < 4; kk4++) {
            const int kbase = kk4 * 2;
            const int cur = kk4 & 1, nxt = cur ^ 1;

            if (kk4 < 3) {
                #pragma unroll
                for (int nj = 0; nj < 4; nj++) {
                    int row = wn * 64 + nj * 16 + b_row_l;
                    int ch  = (kbase + 2 + b_ksel) ^ (row & 7);
                    ldsm_x4(b[nxt][nj][0], b[nxt][nj][1], b[nxt][nj][2], b[nxt][nj][3],
                            sb + row * TBK + ch * 8);
                }
            }

            uint32_t a[2][4];
            #pragma unroll
            for (int mi = 0; mi < 2; mi++) {
                int row = wm * 32 + mi * 16 + a_row_l;
                int ch  = (kbase + a_ksel) ^ (row & 7);
                ldsm_x4(a[mi][0], a[mi][1], a[mi][2], a[mi][3],
                        sa + row * TBK + ch * 8);
            }
            #pragma unroll
            for (int mi = 0; mi < 2; mi++)
                #pragma unroll
                for (int nj = 0; nj < 4; nj++) {
                    mma16816(acc[mi][nj * 2 + 0],
                             a[mi][0], a[mi][1], a[mi][2], a[mi][3],
                             b[cur][nj][0], b[cur][nj][1]);
                    mma16816(acc[mi][nj * 2 + 1],
                             a[mi][0], a[mi][1], a[mi][2], a[mi][3],
                             b[cur][nj][2], b[cur][nj][3]);
                }
        }
    }

    __syncthreads();

    if constexpr (sizeof(OutT) == 2) {
        // fp16 epilogue: add bias in regs, stage half2, copy out 16B chunks
        __half* epsH = (__half*)smem_raw;
        {
            int r = lane >> 2;
            int cc = (lane & 3) * 2;
            #pragma unroll
            for (int mi = 0; mi < 2; mi++) {
                int row0 = wm * 32 + mi * 16;
                #pragma unroll
                for (int nj = 0; nj < 8; nj++) {
                    int col0 = wn * 64 + nj * 8 + cc;
                    float2 bv = *(const float2*)(bias + col0);
                    __half2 h0 = __floats2half2_rn(acc[mi][nj][0] + bv.x,
                                                   acc[mi][nj][1] + bv.y);
                    __half2 h1 = __floats2half2_rn(acc[mi][nj][2] + bv.x,
                                                   acc[mi][nj][3] + bv.y);
                    *(__half2*)(epsH + (size_t)(row0 + r) * EPI_LDH + col0) = h0;
                    *(__half2*)(epsH + (size_t)(row0 + r + 8) * EPI_LDH + col0) = h1;
                }
            }
        }
        __syncthreads();
        #pragma unroll
        for (int u = 0; u < 8; u++) {
            int idx = tid + u * 256;          // 0..2047
            int row = idx >> 4;               // 0..127
            int c8  = (idx & 15) * 8;         // 0..120
            *(uint4*)((__half*)Cb + (size_t)row * ldc + c8) =
                *(const uint4*)(epsH + (size_t)row * EPI_LDH + c8);
        }
    } else {
        // fp32 epilogue with residual
        float* eps = (float*)smem_raw;
        {
            int r = lane >> 2;
            int cc = (lane & 3) * 2;
            #pragma unroll
            for (int mi = 0; mi < 2; mi++) {
                int row0 = wm * 32 + mi * 16;
                #pragma unroll
                for (int nj = 0; nj < 8; nj++) {
                    int col0 = wn * 64 + nj * 8 + cc;
                    float* e0 = eps + (size_t)(row0 + r) * EPI_LD + col0;
                    float* e1 = eps + (size_t)(row0 + r + 8) * EPI_LD + col0;
                    e0[0] = acc[mi][nj][0];
                    e0[1] = acc[mi][nj][1];
                    e1[0] = acc[mi][nj][2];
                    e1[1] = acc[mi][nj][3];
                }
            }
        }
        __syncthreads();
        #pragma unroll
        for (int u = 0; u < 16; u++) {
            int idx = tid + u * 256;
            int row = idx >> 5;
            int c4  = (idx & 31) * 4;
            const float* ep = eps + (size_t)row * EPI_LD + c4;
            float4 bv = *(const float4*)(bias + c4);
            float4 o;
            o.x = ep[0] + bv.x;
            o.y = ep[1] + bv.y;
            o.z = ep[2] + bv.z;
            o.w = ep[3] + bv.w;
            float4 rv = *(const float4*)(resid + (size_t)row * DM + c4);
            o.x += rv.x; o.y += rv.y; o.z += rv.z; o.w += rv.w;
            *(float4*)((float*)Cb + (size_t)row * ldc + c4) = o;
        }
    }
}

// ---------------------------------------------------------------------------
// Fused QKV GEMM: grid (48, 384). blockIdx.x selects matrix (Q/K/V) + column.
// ---------------------------------------------------------------------------
__global__ void __launch_bounds__(256, 2) gemm_qkv_kernel(
    const __half* __restrict__ A, const __half* __restrict__ Wcat,
    const float* __restrict__ bq, const float* __restrict__ bk,
    const float* __restrict__ bv,
    __half* __restrict__ Q, __half* __restrict__ K, __half* __restrict__ V)
{
    extern __shared__ __align__(16) char smem_raw[];
    const int which = blockIdx.x >> 4;              // 0=Q, 1=K, 2=V
    const int ncol  = (blockIdx.x & 15) * TBN;
    const int m0    = blockIdx.y * TBM;

    const __half* Ab = A + (size_t)m0 * DM;
    const __half* Wb = Wcat + ((size_t)which * DM + ncol) * DM;
    const float*  bs = (which == 0) ? bq : (which == 1) ? bk : bv;
    __half* Cb = ((which == 0) ? Q : (which == 1) ? K : V)
               + (size_t)m0 * DM + ncol;

    gemm_tile<__half>(Ab, Wb, bs + ncol, nullptr, Cb, DM, smem_raw, threadIdx.x);
}

// ---------------------------------------------------------------------------
// Output projection GEMM (+bias +residual), fp32 out: grid (16, 384)
// ---------------------------------------------------------------------------
__global__ void __launch_bounds__(256, 2) gemm_o_kernel(
    const __half* __restrict__ A, const __half* __restrict__ W,
    const float* __restrict__ bias, const float* __restrict__ resid,
    float* __restrict__ C)
{
    extern __shared__ __align__(16) char smem_raw[];
    const int ncol = blockIdx.x * TBN;
    const int m0   = blockIdx.y * TBM;

    gemm_tile<float>(A + (size_t)m0 * DM,
                     W + (size_t)ncol * DM,
                     bias + ncol,
                     resid + (size_t)m0 * DM + ncol,
                     C + (size_t)m0 * DM + ncol,
                     DM, smem_raw, threadIdx.x);
}

// ---------------------------------------------------------------------------
// Attention: one warp per (batch, head). S=6, DH=128; lane owns 4 head dims.
// Precomputed mask = sigmoid(routing)/sqrt(DH); __expf softmax; V-load overlap.
// ---------------------------------------------------------------------------
__global__ void __launch_bounds__(128) attn_kernel(
    const __half* __restrict__ Q, const __half* __restrict__ K,
    const __half* __restrict__ V, const float* __restrict__ mask,
    __half* __restrict__ O)
{
    int wg   = blockIdx.x * 4 + (threadIdx.x >> 5);
    int lane = threadIdx.x & 31;
    int b = wg >> 4, h = wg & 15;
    size_t base = (size_t)b * SEQ * DM + (size_t)h * DH + lane * 4;

    float4 q[SEQ], k[SEQ];
    #pragma unroll
    for (int s = 0; s < SEQ; s++) {
        const __half2* qp = (const __half2*)(Q + base + (size_t)s * DM);
        const __half2* kp = (const __half2*)(K + base + (size_t)s * DM);
        float2 q0 = __half22float2(qp[0]), q1 = __half22float2(qp[1]);
        float2 k0 = __half22float2(kp[0]), k1 = __half22float2(kp[1]);
        q[s] = make_float4(q0.x, q0.y, q1.x, q1.y);
        k[s] = make_float4(k0.x, k0.y, k1.x, k1.y);
    }

    float sc[SEQ * SEQ];
    #pragma unroll
    for (int i = 0; i < SEQ; i++)
        #pragma unroll
        for (int j = 0; j < SEQ; j++)
            sc[i * SEQ + j] = q[i].x * k[j].x + q[i].y * k[j].y
                            + q[i].z * k[j].z + q[i].w * k[j].w;

    // kick off V loads; latency hidden under the shuffle chain
    uint2 vraw[SEQ];
    #pragma unroll
    for (int s = 0; s < SEQ; s++)
        vraw[s] = *(const uint2*)(V + base + (size_t)s * DM);

    #pragma unroll
    for (int t = 0; t < SEQ * SEQ; t++)
        #pragma unroll
        for (int o = 16; o; o >>= 1)
            sc[t] += __shfl_xor_sync(0xffffffffu, sc[t], o);

    #pragma unroll
    for (int i = 0; i < SEQ; i++)
        #pragma unroll
        for (int j = 0; j < SEQ; j++)
            sc[i * SEQ + j] *= __ldg(mask + i * SEQ + j);

    #pragma unroll
    for (int i = 0; i < SEQ; i++) {
        float mx = sc[i * SEQ];
        #pragma unroll
        for (int j = 1; j < SEQ; j++) mx = fmaxf(mx, sc[i * SEQ + j]);
        float sum = 0.f;
        #pragma unroll
        for (int j = 0; j < SEQ; j++) {
            sc[i * SEQ + j] = __expf(sc[i * SEQ + j] - mx);
            sum += sc[i * SEQ + j];
        }
        float rs = 1.f / sum;
        #pragma unroll
        for (int j = 0; j < SEQ; j++) sc[i * SEQ + j] *= rs;
    }

    float4 v[SEQ];
    #pragma unroll
    for (int s = 0; s < SEQ; s++) {
        __half2 h0 = *(__half2*)&vraw[s].x;
        __half2 h1 = *(__half2*)&vraw[s].y;
        float2 v0 = __half22float2(h0), v1 = __half22float2(h1);
        v[s] = make_float4(v0.x, v0.y, v1.x, v1.y);
    }

    #pragma unroll
    for (int i = 0; i < SEQ; i++) {
        float4 o = make_float4(0.f, 0.f, 0.f, 0.f);
        #pragma unroll
        for (int j = 0; j < SEQ; j++) {
            float p = sc[i * SEQ + j];
            o.x += p * v[j].x; o.y += p * v[j].y;
            o.z += p * v[j].z; o.w += p * v[j].w;
        }
        __half2* dst = (__half2*)(O + base + (size_t)i * DM);
        dst[0] = __floats2half2_rn(o.x, o.y);
        dst[1] = __floats2half2_rn(o.z, o.w);
    }
}

// ---------------------------------------------------------------------------
// kernel_launch
// inputs: 0 stream_embeddings, 1 Wq, 2 bq, 3 Wk, 4 bk, 5 Wv, 6 bv,
//         7 Wo, 8 bo, 9 routing_logits, 10 gamma, 11 beta
// ---------------------------------------------------------------------------
extern "C" void kernel_launch(void* const* d_in, const int* in_sizes, int n_in,
                              void* d_out, int out_size)
{
    (void)in_sizes; (void)n_in; (void)out_size;
    const float* x       = (const float*)d_in[0];
    const float* Wq      = (const float*)d_in[1];
    const float* bq      = (const float*)d_in[2];
    const float* Wk      = (const float*)d_in[3];
    const float* bk      = (const float*)d_in[4];
    const float* Wv      = (const float*)d_in[5];
    const float* bv      = (const float*)d_in[6];
    const float* Wo      = (const float*)d_in[7];
    const float* bo      = (const float*)d_in[8];
    const float* routing = (const float*)d_in[9];
    const float* gamma   = (const float*)d_in[10];
    const float* beta    = (const float*)d_in[11];
    float* out = (float*)d_out;

    __half *Xh, *Qb, *Kb, *Vb, *Wh;
    float* maskp;
    cudaGetSymbolAddress((void**)&Xh, g_Xh);
    cudaGetSymbolAddress((void**)&Qb, g_Q);
    cudaGetSymbolAddress((void**)&Kb, g_K);
    cudaGetSymbolAddress((void**)&Vb, g_V);
    cudaGetSymbolAddress((void**)&Wh, g_Wh);
    cudaGetSymbolAddress((void**)&maskp, g_mask);
    __half* Woh = Wh + 3 * (size_t)DM * DM;

    cudaFuncSetAttribute(gemm_qkv_kernel,
                         cudaFuncAttributeMaxDynamicSharedMemorySize, DYN_SMEM_BYTES);
    cudaFuncSetAttribute(gemm_qkv_kernel,
                         cudaFuncAttributePreferredSharedMemoryCarveout, 100);
    cudaFuncSetAttribute(gemm_o_kernel,
                         cudaFuncAttributeMaxDynamicSharedMemorySize, DYN_SMEM_BYTES);
    cudaFuncSetAttribute(gemm_o_kernel,
                         cudaFuncAttributePreferredSharedMemoryCarveout, 100);

    w2h_all_kernel<<<dim3(512, 4), 256>>>(Wq, Wk, Wv, Wo, Wh);

    ln_kernel<<<TOK, 256>>>(x, gamma, beta, routing, maskp, Xh);

    gemm_qkv_kernel<<<dim3(48, TOK / TBM), 256, DYN_SMEM_BYTES>>>(
        Xh, Wh, bq, bk, bv, Qb, Kb, Vb);

    attn_kernel<<<(NBATCH * NH) / 4, 128>>>(Qb, Kb, Vb, maskp, Xh);

    gemm_o_kernel<<<dim3(16, TOK / TBM), 256, DYN_SMEM_BYTES>>>(
        Xh, Woh, bo, x /*residual*/, out);
}

// round 14
// speedup vs baseline: 1.0294x; 1.0004x over previous
#include <cuda_runtime.h>
#include <cuda_fp16.h>
#include <cstdint>

// ---------------------------------------------------------------------------
// Problem constants
// ---------------------------------------------------------------------------
#define NBATCH 8192
#define SEQ    6
#define TOK    49152        // NBATCH * SEQ
#define DM     2048
#define NH     16
#define DH     128
#define LN_EPS 1e-5f

// w2h merged into LN launch: 512 blocks per weight matrix, 4 matrices
#define W2H_BLOCKS_PER_MAT 512
#define W2H_BLOCKS (W2H_BLOCKS_PER_MAT * 4)    // 2048

// ---------------------------------------------------------------------------
// GEMM tiling: CTA 128x128, BK=64 halves, 3 stages, 256 threads (8 warps 32x64)
// Swizzled smem (no padding): row = 64 halves = 8 x 16B chunks, chunk ^= row&7
// ---------------------------------------------------------------------------
#define TBM 128
#define TBN 128
#define TBK 64
#define STAGES 3
#define KITERS (DM / TBK)                      // 32
#define A_HALVES (TBM * TBK)                   // 8192
#define STAGE_HALVES ((TBM + TBN) * TBK)       // 16384 halves = 32 KB
#define DYN_SMEM_BYTES (STAGES * STAGE_HALVES * 2)   // 98304 B
#define EPI_LD  132                            // fp32 epilogue stride (floats)
#define EPI_LDH 136                            // fp16 epilogue stride (halves)

// ---------------------------------------------------------------------------
// Device-global scratch
// ---------------------------------------------------------------------------
__device__ __align__(256) __half g_Xh[(size_t)TOK * DM];   // LN out / attn out
__device__ __align__(256) __half g_Q[(size_t)TOK * DM];
__device__ __align__(256) __half g_K[(size_t)TOK * DM];
__device__ __align__(256) __half g_V[(size_t)TOK * DM];
__device__ __align__(256) __half g_Wh[4][(size_t)DM * DM]; // fp16 weights (q,k,v,o)
__device__ __align__(16)  float  g_mask[SEQ * SEQ];        // sigmoid(routing)/sqrt(DH)

// ---------------------------------------------------------------------------
// helpers
// ---------------------------------------------------------------------------
__device__ __forceinline__ void cp_async16(void* smem_dst, const void* gmem_src) {
    unsigned s = (unsigned)__cvta_generic_to_shared(smem_dst);
    asm volatile("cp.async.cg.shared.global [%0], [%1], 16;\n" :: "r"(s), "l"(gmem_src));
}
__device__ __forceinline__ void cp_commit() {
    asm volatile("cp.async.commit_group;\n" ::: "memory");
}
template <int N>
__device__ __forceinline__ void cp_wait() {
    asm volatile("cp.async.wait_group %0;\n" :: "n"(N) : "memory");
}
__device__ __forceinline__ void ldsm_x4(uint32_t& d0, uint32_t& d1, uint32_t& d2,
                                        uint32_t& d3, const __half* p) {
    uint32_t a = (uint32_t)__cvta_generic_to_shared(p);
    asm volatile("ldmatrix.sync.aligned.m8n8.x4.shared.b16 {%0,%1,%2,%3}, [%4];"
                 : "=r"(d0), "=r"(d1), "=r"(d2), "=r"(d3) : "r"(a));
}
__device__ __forceinline__ void mma16816(float* c,
                                         uint32_t a0, uint32_t a1, uint32_t a2, uint32_t a3,
                                         uint32_t b0, uint32_t b1) {
    asm volatile("mma.sync.aligned.m16n8k16.row.col.f32.f16.f16.f32 "
                 "{%0,%1,%2,%3}, {%4,%5,%6,%7}, {%8,%9}, {%0,%1,%2,%3};"
                 : "+f"(c[0]), "+f"(c[1]), "+f"(c[2]), "+f"(c[3])
                 : "r"(a0), "r"(a1), "r"(a2), "r"(a3), "r"(b0), "r"(b1));
}

// ---------------------------------------------------------------------------
// Fused LayerNorm + weight-convert + mask precompute (one launch).
//   blocks [0, TOK)            : LN of one token each (fp16 out)
//   blocks [TOK, TOK+W2H_BLOCKS): fp32->fp16 weight conversion (grid-stride)
//   block 0 additionally computes mask = sigmoid(routing)/sqrt(DH)
// ---------------------------------------------------------------------------
__global__ void __launch_bounds__(256) ln_w2h_kernel(
    const float* __restrict__ x, const float* __restrict__ gamma,
    const float* __restrict__ beta, const float* __restrict__ routing,
    const float* __restrict__ w0, const float* __restrict__ w1,
    const float* __restrict__ w2, const float* __restrict__ w3,
    __half* __restrict__ wOut, float* __restrict__ maskOut,
    __half* __restrict__ out)
{
    int tid = threadIdx.x;

    if (blockIdx.x >= TOK) {
        // ---- weight conversion path ----
        int wb    = blockIdx.x - TOK;
        int which = wb >> 9;                    // 0..3
        int lb    = wb & (W2H_BLOCKS_PER_MAT - 1);
        const float* src_f = (which == 0) ? w0 : (which == 1) ? w1
                           : (which == 2) ? w2 : w3;
        __half* dst_h = wOut + (size_t)which * DM * DM;
        const int n4 = DM * DM / 4;
        const float4* src = (const float4*)src_f;
        __half2* dst = (__half2*)dst_h;
        for (int i = lb * 256 + tid; i < n4; i += W2H_BLOCKS_PER_MAT * 256) {
            float4 v = src[i];
            dst[i * 2 + 0] = __floats2half2_rn(v.x, v.y);
            dst[i * 2 + 1] = __floats2half2_rn(v.z, v.w);
        }
        return;
    }

    // ---- LayerNorm path ----
    int t = blockIdx.x;

    if (t == 0 && tid < SEQ * SEQ) {
        float r = routing[tid];
        maskOut[tid] = 0.08838834764831845f / (1.f + __expf(-r));
    }

    const float4* xr = (const float4*)(x + (size_t)t * DM);

    float4 a = xr[tid];
    float4 b = xr[tid + 256];
    float s  = a.x + a.y + a.z + a.w + b.x + b.y + b.z + b.w;
    float ss = a.x*a.x + a.y*a.y + a.z*a.z + a.w*a.w
             + b.x*b.x + b.y*b.y + b.z*b.z + b.w*b.w;

    __shared__ float red[2][8];
    #pragma unroll
    for (int o = 16; o; o >>= 1) {
        s  += __shfl_xor_sync(0xffffffffu, s,  o);
        ss += __shfl_xor_sync(0xffffffffu, ss, o);
    }
    int wid = tid >> 5, lane = tid & 31;
    if (lane == 0) { red[0][wid] = s; red[1][wid] = ss; }
    __syncthreads();

    float st = 0.f, sst = 0.f;
    #pragma unroll
    for (int i = 0; i < 8; i++) { st += red[0][i]; sst += red[1][i]; }

    float mu  = st * (1.f / DM);
    float var = sst * (1.f / DM) - mu * mu;
    float inv = rsqrtf(var + LN_EPS);

    const float4* g4 = (const float4*)gamma;
    const float4* b4 = (const float4*)beta;
    __half2* o2 = (__half2*)(out + (size_t)t * DM);

    float4 ga = g4[tid],       ba = b4[tid];
    float4 gb = g4[tid + 256], bb = b4[tid + 256];
    o2[tid * 2 + 0] = __floats2half2_rn((a.x - mu) * inv * ga.x + ba.x,
                                        (a.y - mu) * inv * ga.y + ba.y);
    o2[tid * 2 + 1] = __floats2half2_rn((a.z - mu) * inv * ga.z + ba.z,
                                        (a.w - mu) * inv * ga.w + ba.w);
    o2[(tid + 256) * 2 + 0] = __floats2half2_rn((b.x - mu) * inv * gb.x + bb.x,
                                                (b.y - mu) * inv * gb.y + bb.y);
    o2[(tid + 256) * 2 + 1] = __floats2half2_rn((b.z - mu) * inv * gb.z + bb.z,
                                                (b.w - mu) * inv * gb.w + bb.w);
}

// ---------------------------------------------------------------------------
// Core fp16 mma GEMM body (R8/R10-proven schedule): one 128x128 tile.
// 8 warps: wm = wid&3 (32 rows), wn = wid>>2 (64 cols). 3-stage cp.async,
// one __syncthreads per k-iter, B-fragment ping-pong prefetch. No K-phase
// rotation: co-resident CTAs sweeping the same K-slice is what gives the
// fused-QKV launch its L2 temporal locality (R11 post-mortem).
// ---------------------------------------------------------------------------
template <typename OutT>
__device__ __forceinline__ void gemm_tile(
    const __half* __restrict__ Ab,   // A + m0*DM
    const __half* __restrict__ Wb,   // W row block
    const float* __restrict__ bias,  // bias + n0 (block of 128)
    const float* __restrict__ resid, // resid + m0*DM + n0, or null
    OutT* __restrict__ Cb,           // C + m0*ldc + n0
    int ldc, char* smem_raw, int tid)
{
    __half* smem = (__half*)smem_raw;
    const int wid  = tid >> 5;
    const int lane = tid & 31;
    const int wm   = wid & 3;
    const int wn   = wid >> 2;

    float acc[2][8][4];
    #pragma unroll
    for (int i = 0; i < 2; i++)
        #pragma unroll
        for (int j = 0; j < 8; j++)
            #pragma unroll
            for (int e = 0; e < 4; e++)
                acc[i][j][e] = 0.f;

    const int a_row_l = lane & 15;
    const int a_ksel  = lane >> 4;
    const int b_row_l = ((lane >> 4) << 3) | (lane & 7);
    const int b_ksel  = (lane >> 3) & 1;

    auto load_stage = [&](int buf, int st) {
        __half* sa = smem + (size_t)buf * STAGE_HALVES;
        __half* sb = sa + A_HALVES;
        int k0 = st * TBK;
        #pragma unroll
        for (int u = 0; u < 4; u++) {
            int idx = tid + u * 256;
            int row = idx >> 3, c = idx & 7;
            int pc  = c ^ (row & 7);
            cp_async16(sa + row * TBK + pc * 8, Ab + (size_t)row * DM + k0 + c * 8);
        }
        #pragma unroll
        for (int u = 0; u < 4; u++) {
            int idx = tid + u * 256;
            int row = idx >> 3, c = idx & 7;
            int pc  = c ^ (row & 7);
            cp_async16(sb + row * TBK + pc * 8, Wb + (size_t)row * DM + k0 + c * 8);
        }
    };

    load_stage(0, 0); cp_commit();
    load_stage(1, 1); cp_commit();

    for (int k = 0; k < KITERS; k++) {
        int buf = k % STAGES;
        cp_wait<STAGES - 2>();
        __syncthreads();

        if (k + 2 < KITERS) load_stage((k + 2) % STAGES, k + 2);
        cp_commit();

        const __half* sa = smem + (size_t)buf * STAGE_HALVES;
        const __half* sb = sa + A_HALVES;

        // B ping-pong prefetch across 4 k16 steps
        uint32_t b[2][4][4];
        #pragma unroll
        for (int nj = 0; nj < 4; nj++) {
            int row = wn * 64 + nj * 16 + b_row_l;
            int ch  = (0 + b_ksel) ^ (row & 7);
            ldsm_x4(b[0][nj][0], b[0][nj][1], b[0][nj][2], b[0][nj][3],
                    sb + row * TBK + ch * 8);
        }

        #pragma unroll
        for (int kk4 = 0; kk4 < 4; kk4++) {
            const int kbase = kk4 * 2;
            const int cur = kk4 & 1, nxt = cur ^ 1;

            if (kk4 < 3) {
                #pragma unroll
                for (int nj = 0; nj < 4; nj++) {
                    int row = wn * 64 + nj * 16 + b_row_l;
                    int ch  = (kbase + 2 + b_ksel) ^ (row & 7);
                    ldsm_x4(b[nxt][nj][0], b[nxt][nj][1], b[nxt][nj][2], b[nxt][nj][3],
                            sb + row * TBK + ch * 8);
                }
            }

            uint32_t a[2][4];
            #pragma unroll
            for (int mi = 0; mi < 2; mi++) {
                int row = wm * 32 + mi * 16 + a_row_l;
                int ch  = (kbase + a_ksel) ^ (row & 7);
                ldsm_x4(a[mi][0], a[mi][1], a[mi][2], a[mi][3],
                        sa + row * TBK + ch * 8);
            }
            #pragma unroll
            for (int mi = 0; mi < 2; mi++)
                #pragma unroll
                for (int nj = 0; nj < 4; nj++) {
                    mma16816(acc[mi][nj * 2 + 0],
                             a[mi][0], a[mi][1], a[mi][2], a[mi][3],
                             b[cur][nj][0], b[cur][nj][1]);
                    mma16816(acc[mi][nj * 2 + 1],
                             a[mi][0], a[mi][1], a[mi][2], a[mi][3],
                             b[cur][nj][2], b[cur][nj][3]);
                }
        }
    }

    __syncthreads();

    if constexpr (sizeof(OutT) == 2) {
        // fp16 epilogue: add bias in regs, stage half2, copy out 16B chunks
        __half* epsH = (__half*)smem_raw;
        {
            int r = lane >> 2;
            int cc = (lane & 3) * 2;
            #pragma unroll
            for (int mi = 0; mi < 2; mi++) {
                int row0 = wm * 32 + mi * 16;
                #pragma unroll
                for (int nj = 0; nj < 8; nj++) {
                    int col0 = wn * 64 + nj * 8 + cc;
                    float2 bv = *(const float2*)(bias + col0);
                    __half2 h0 = __floats2half2_rn(acc[mi][nj][0] + bv.x,
                                                   acc[mi][nj][1] + bv.y);
                    __half2 h1 = __floats2half2_rn(acc[mi][nj][2] + bv.x,
                                                   acc[mi][nj][3] + bv.y);
                    *(__half2*)(epsH + (size_t)(row0 + r) * EPI_LDH + col0) = h0;
                    *(__half2*)(epsH + (size_t)(row0 + r + 8) * EPI_LDH + col0) = h1;
                }
            }
        }
        __syncthreads();
        #pragma unroll
        for (int u = 0; u < 8; u++) {
            int idx = tid + u * 256;          // 0..2047
            int row = idx >> 4;               // 0..127
            int c8  = (idx & 15) * 8;         // 0..120
            *(uint4*)((__half*)Cb + (size_t)row * ldc + c8) =
                *(const uint4*)(epsH + (size_t)row * EPI_LDH + c8);
        }
    } else {
        // fp32 epilogue with residual
        float* eps = (float*)smem_raw;
        {
            int r = lane >> 2;
            int cc = (lane & 3) * 2;
            #pragma unroll
            for (int mi = 0; mi < 2; mi++) {
                int row0 = wm * 32 + mi * 16;
                #pragma unroll
                for (int nj = 0; nj < 8; nj++) {
                    int col0 = wn * 64 + nj * 8 + cc;
                    float* e0 = eps + (size_t)(row0 + r) * EPI_LD + col0;
                    float* e1 = eps + (size_t)(row0 + r + 8) * EPI_LD + col0;
                    e0[0] = acc[mi][nj][0];
                    e0[1] = acc[mi][nj][1];
                    e1[0] = acc[mi][nj][2];
                    e1[1] = acc[mi][nj][3];
                }
            }
        }
        __syncthreads();
        #pragma unroll
        for (int u = 0; u < 16; u++) {
            int idx = tid + u * 256;
            int row = idx >> 5;
            int c4  = (idx & 31) * 4;
            const float* ep = eps + (size_t)row * EPI_LD + c4;
            float4 bv = *(const float4*)(bias + c4);
            float4 o;
            o.x = ep[0] + bv.x;
            o.y = ep[1] + bv.y;
            o.z = ep[2] + bv.z;
            o.w = ep[3] + bv.w;
            float4 rv = *(const float4*)(resid + (size_t)row * DM + c4);
            o.x += rv.x; o.y += rv.y; o.z += rv.z; o.w += rv.w;
            *(float4*)((float*)Cb + (size_t)row * ldc + c4) = o;
        }
    }
}

// ---------------------------------------------------------------------------
// Fused QKV GEMM: grid (48, 384). blockIdx.x selects matrix (Q/K/V) + column.
// ---------------------------------------------------------------------------
__global__ void __launch_bounds__(256, 2) gemm_qkv_kernel(
    const __half* __restrict__ A, const __half* __restrict__ Wcat,
    const float* __restrict__ bq, const float* __restrict__ bk,
    const float* __restrict__ bv,
    __half* __restrict__ Q, __half* __restrict__ K, __half* __restrict__ V)
{
    extern __shared__ __align__(16) char smem_raw[];
    const int which = blockIdx.x >> 4;              // 0=Q, 1=K, 2=V
    const int ncol  = (blockIdx.x & 15) * TBN;
    const int m0    = blockIdx.y * TBM;

    const __half* Ab = A + (size_t)m0 * DM;
    const __half* Wb = Wcat + ((size_t)which * DM + ncol) * DM;
    const float*  bs = (which == 0) ? bq : (which == 1) ? bk : bv;
    __half* Cb = ((which == 0) ? Q : (which == 1) ? K : V)
               + (size_t)m0 * DM + ncol;

    gemm_tile<__half>(Ab, Wb, bs + ncol, nullptr, Cb, DM, smem_raw, threadIdx.x);
}

// ---------------------------------------------------------------------------
// Output projection GEMM (+bias +residual), fp32 out: grid (16, 384)
// ---------------------------------------------------------------------------
__global__ void __launch_bounds__(256, 2) gemm_o_kernel(
    const __half* __restrict__ A, const __half* __restrict__ W,
    const float* __restrict__ bias, const float* __restrict__ resid,
    float* __restrict__ C)
{
    extern __shared__ __align__(16) char smem_raw[];
    const int ncol = blockIdx.x * TBN;
    const int m0   = blockIdx.y * TBM;

    gemm_tile<float>(A + (size_t)m0 * DM,
                     W + (size_t)ncol * DM,
                     bias + ncol,
                     resid + (size_t)m0 * DM + ncol,
                     C + (size_t)m0 * DM + ncol,
                     DM, smem_raw, threadIdx.x);
}

// ---------------------------------------------------------------------------
// Attention: one warp per (batch, head). S=6, DH=128; lane owns 4 head dims.
// Precomputed mask = sigmoid(routing)/sqrt(DH); __expf softmax; V-load overlap.
// ---------------------------------------------------------------------------
__global__ void __launch_bounds__(128) attn_kernel(
    const __half* __restrict__ Q, const __half* __restrict__ K,
    const __half* __restrict__ V, const float* __restrict__ mask,
    __half* __restrict__ O)
{
    int wg   = blockIdx.x * 4 + (threadIdx.x >> 5);
    int lane = threadIdx.x & 31;
    int b = wg >> 4, h = wg & 15;
    size_t base = (size_t)b * SEQ * DM + (size_t)h * DH + lane * 4;

    float4 q[SEQ], k[SEQ];
    #pragma unroll
    for (int s = 0; s < SEQ; s++) {
        const __half2* qp = (const __half2*)(Q + base + (size_t)s * DM);
        const __half2* kp = (const __half2*)(K + base + (size_t)s * DM);
        float2 q0 = __half22float2(qp[0]), q1 = __half22float2(qp[1]);
        float2 k0 = __half22float2(kp[0]), k1 = __half22float2(kp[1]);
        q[s] = make_float4(q0.x, q0.y, q1.x, q1.y);
        k[s] = make_float4(k0.x, k0.y, k1.x, k1.y);
    }

    float sc[SEQ * SEQ];
    #pragma unroll
    for (int i = 0; i < SEQ; i++)
        #pragma unroll
        for (int j = 0; j < SEQ; j++)
            sc[i * SEQ + j] = q[i].x * k[j].x + q[i].y * k[j].y
                            + q[i].z * k[j].z + q[i].w * k[j].w;

    // kick off V loads; latency hidden under the shuffle chain
    uint2 vraw[SEQ];
    #pragma unroll
    for (int s = 0; s < SEQ; s++)
        vraw[s] = *(const uint2*)(V + base + (size_t)s * DM);

    #pragma unroll
    for (int t = 0; t < SEQ * SEQ; t++)
        #pragma unroll
        for (int o = 16; o; o >>= 1)
            sc[t] += __shfl_xor_sync(0xffffffffu, sc[t], o);

    #pragma unroll
    for (int i = 0; i < SEQ; i++)
        #pragma unroll
        for (int j = 0; j < SEQ; j++)
            sc[i * SEQ + j] *= __ldg(mask + i * SEQ + j);

    #pragma unroll
    for (int i = 0; i < SEQ; i++) {
        float mx = sc[i * SEQ];
        #pragma unroll
        for (int j = 1; j < SEQ; j++) mx = fmaxf(mx, sc[i * SEQ + j]);
        float sum = 0.f;
        #pragma unroll
        for (int j = 0; j < SEQ; j++) {
            sc[i * SEQ + j] = __expf(sc[i * SEQ + j] - mx);
            sum += sc[i * SEQ + j];
        }
        float rs = 1.f / sum;
        #pragma unroll
        for (int j = 0; j < SEQ; j++) sc[i * SEQ + j] *= rs;
    }

    float4 v[SEQ];
    #pragma unroll
    for (int s = 0; s < SEQ; s++) {
        __half2 h0 = *(__half2*)&vraw[s].x;
        __half2 h1 = *(__half2*)&vraw[s].y;
        float2 v0 = __half22float2(h0), v1 = __half22float2(h1);
        v[s] = make_float4(v0.x, v0.y, v1.x, v1.y);
    }

    #pragma unroll
    for (int i = 0; i < SEQ; i++) {
        float4 o = make_float4(0.f, 0.f, 0.f, 0.f);
        #pragma unroll
        for (int j = 0; j < SEQ; j++) {
            float p = sc[i * SEQ + j];
            o.x += p * v[j].x; o.y += p * v[j].y;
            o.z += p * v[j].z; o.w += p * v[j].w;
        }
        __half2* dst = (__half2*)(O + base + (size_t)i * DM);
        dst[0] = __floats2half2_rn(o.x, o.y);
        dst[1] = __floats2half2_rn(o.z, o.w);
    }
}

// ---------------------------------------------------------------------------
// kernel_launch
// inputs: 0 stream_embeddings, 1 Wq, 2 bq, 3 Wk, 4 bk, 5 Wv, 6 bv,
//         7 Wo, 8 bo, 9 routing_logits, 10 gamma, 11 beta
// ---------------------------------------------------------------------------
extern "C" void kernel_launch(void* const* d_in, const int* in_sizes, int n_in,
                              void* d_out, int out_size)
{
    (void)in_sizes; (void)n_in; (void)out_size;
    const float* x       = (const float*)d_in[0];
    const float* Wq      = (const float*)d_in[1];
    const float* bq      = (const float*)d_in[2];
    const float* Wk      = (const float*)d_in[3];
    const float* bk      = (const float*)d_in[4];
    const float* Wv      = (const float*)d_in[5];
    const float* bv      = (const float*)d_in[6];
    const float* Wo      = (const float*)d_in[7];
    const float* bo      = (const float*)d_in[8];
    const float* routing = (const float*)d_in[9];
    const float* gamma   = (const float*)d_in[10];
    const float* beta    = (const float*)d_in[11];
    float* out = (float*)d_out;

    __half *Xh, *Qb, *Kb, *Vb, *Wh;
    float* maskp;
    cudaGetSymbolAddress((void**)&Xh, g_Xh);
    cudaGetSymbolAddress((void**)&Qb, g_Q);
    cudaGetSymbolAddress((void**)&Kb, g_K);
    cudaGetSymbolAddress((void**)&Vb, g_V);
    cudaGetSymbolAddress((void**)&Wh, g_Wh);
    cudaGetSymbolAddress((void**)&maskp, g_mask);
    __half* Woh = Wh + 3 * (size_t)DM * DM;

    cudaFuncSetAttribute(gemm_qkv_kernel,
                         cudaFuncAttributeMaxDynamicSharedMemorySize, DYN_SMEM_BYTES);
    cudaFuncSetAttribute(gemm_qkv_kernel,
                         cudaFuncAttributePreferredSharedMemoryCarveout, 100);
    cudaFuncSetAttribute(gemm_o_kernel,
                         cudaFuncAttributeMaxDynamicSharedMemorySize, DYN_SMEM_BYTES);
    cudaFuncSetAttribute(gemm_o_kernel,
                         cudaFuncAttributePreferredSharedMemoryCarveout, 100);

    // LN + weight convert + mask, all in one launch
    ln_w2h_kernel<<<TOK + W2H_BLOCKS, 256>>>(
        x, gamma, beta, routing, Wq, Wk, Wv, Wo, Wh, maskp, Xh);

    gemm_qkv_kernel<<<dim3(48, TOK / TBM), 256, DYN_SMEM_BYTES>>>(
        Xh, Wh, bq, bk, bv, Qb, Kb, Vb);

    attn_kernel<<<(NBATCH * NH) / 4, 128>>>(Qb, Kb, Vb, maskp, Xh);

    gemm_o_kernel<<<dim3(16, TOK / TBM), 256, DYN_SMEM_BYTES>>>(
        Xh, Woh, bo, x /*residual*/, out);
}